// round 2
// baseline (speedup 1.0000x reference)
#include <cuda_runtime.h>

#define NN 10000
#define NE 320000
#define FULLM 0xffffffffu

// ---------------- scratch (static device memory; no allocation) ----------------
__device__ __align__(16) float g_q[NN * 64];        // q_src | q_dst per node
__device__ __align__(16) float g_v[NN * 576];       // v_nodes [N][9*64]
__device__ __align__(16) float g_logits[NE * 8];    // edge logits
__device__ __align__(16) float g_agg[NN * 576];     // aggregated messages
__device__ __align__(16) float g_p[NN * 64];        // p_src | p_dst per node (edge MLP2 hoist)
__device__ float g_maskf[NN];
__device__ int g_mtype;
__device__ int g_deg[NN];
__device__ int g_cur[NN];
__device__ int g_off[NN + 1];
__device__ int g_csr[NE];

// ---------------- f32x2 helpers ----------------
static __device__ __forceinline__ unsigned long long pack2(float x, float y) {
    unsigned long long r; asm("mov.b64 %0, {%1,%2};" : "=l"(r) : "f"(x), "f"(y)); return r;
}
static __device__ __forceinline__ unsigned long long dup2(float x) {
    unsigned long long r; asm("mov.b64 %0, {%1,%1};" : "=l"(r) : "f"(x)); return r;
}
static __device__ __forceinline__ void unpack2(unsigned long long v, float& x, float& y) {
    asm("mov.b64 {%0,%1}, %2;" : "=f"(x), "=f"(y) : "l"(v));
}
static __device__ __forceinline__ void ffma2(unsigned long long& d, unsigned long long a, unsigned long long b) {
    asm("fma.rn.f32x2 %0, %1, %2, %0;" : "+l"(d) : "l"(a), "l"(b));
}
static __device__ __forceinline__ float silu_f(float x) { return x / (1.f + __expf(-x)); }

// ---------------- mask dtype detection + conversion ----------------
// Reads exactly 10000 bytes (2500 words) — safe whether the buffer holds
// 10000 uint8, 10000 int32, or 10000 float32 elements.
__global__ void k_mask_detect(const void* __restrict__ p) {
    const unsigned* u = (const unsigned*)p;
    __shared__ int okf, oki;
    if (threadIdx.x == 0) { okf = 1; oki = 1; }
    __syncthreads();
    for (int i = threadIdx.x; i < 2500; i += 256) {
        unsigned v = u[i];
        if (!(v == 0u || v == 0x3F800000u)) okf = 0;
        if (!(v == 0u || v == 1u)) oki = 0;
    }
    __syncthreads();
    if (threadIdx.x == 0) g_mtype = okf ? 0 : (oki ? 1 : 2);
}

__global__ void k_mask_conv(const void* __restrict__ p) {
    int i = blockIdx.x * 256 + threadIdx.x;
    if (i >= NN) return;
    int t = g_mtype;
    float m;
    if (t == 0) m = ((const float*)p)[i];
    else if (t == 1) m = (float)(((const int*)p)[i] != 0);
    else m = ((const unsigned char*)p)[i] ? 1.f : 0.f;
    g_maskf[i] = m;
}

// ---------------- init ----------------
__global__ void k_init() {
    int i = blockIdx.x * blockDim.x + threadIdx.x;
    if (i < NN) { g_deg[i] = 0; g_cur[i] = 0; }
}

// ---------------- node prep: q = inv@Wa1[:70] halves, v = node@Wv ----------------
__global__ __launch_bounds__(256) void k_node_prep(
    const float* __restrict__ bb_emb, const float* __restrict__ bb_rel,
    const float* __restrict__ Wa1, const float* __restrict__ Wv) {
    __shared__ float sWv[35 * 64];
    __shared__ float sWa[70 * 32];
    int tid = threadIdx.x;
    for (int i = tid; i < 35 * 64; i += 256) sWv[i] = Wv[i];
    for (int i = tid; i < 70 * 32; i += 256) sWa[i] = Wa1[i];
    __syncthreads();
    int lane = tid & 31;
    int n = blockIdx.x * 8 + (tid >> 5);
    float mk = g_maskf[n];

    // q_src / q_dst  (inv = [bb_emb[n,0,:32], 0, 0, mask])
    float r0 = bb_emb[n * 288 + lane];
    float qs = mk * sWa[34 * 32 + lane];
    float qd = mk * sWa[69 * 32 + lane];
#pragma unroll
    for (int k = 0; k < 32; k++) {
        float b = __shfl_sync(FULLM, r0, k);
        qs += b * sWa[k * 32 + lane];
        qd += b * sWa[(35 + k) * 32 + lane];
    }
    g_q[n * 64 + lane] = qs;
    g_q[n * 64 + 32 + lane] = qd;

    // v_nodes
#pragma unroll
    for (int c = 0; c < 9; c++) {
        float f = bb_emb[n * 288 + c * 32 + lane];
        float a0 = 0.f, a1 = 0.f;
        if (c == 0) {
            a0 = mk * sWv[34 * 64 + lane];
            a1 = mk * sWv[34 * 64 + 32 + lane];
        } else if (c <= 3) {
#pragma unroll
            for (int b = 0; b < 3; b++) {
                float rr = bb_rel[n * 9 + b * 3 + (c - 1)];
                a0 += rr * sWv[(32 + b) * 64 + lane];
                a1 += rr * sWv[(32 + b) * 64 + 32 + lane];
            }
        }
#pragma unroll
        for (int k = 0; k < 32; k++) {
            float t = __shfl_sync(FULLM, f, k);
            a0 += t * sWv[k * 64 + lane];
            a1 += t * sWv[k * 64 + 32 + lane];
        }
        g_v[n * 576 + c * 64 + lane] = a0;
        g_v[n * 576 + c * 64 + 32 + lane] = a1;
    }
}

// ---------------- CSR build ----------------
__global__ void k_count(const int* __restrict__ ei) {
    int e = blockIdx.x * 256 + threadIdx.x;
    atomicAdd(&g_deg[ei[NE + e]], 1);
}

__global__ void k_scan() {
    __shared__ int sh[1024];
    __shared__ int carry;
    if (threadIdx.x == 0) carry = 0;
    __syncthreads();
    for (int base = 0; base < NN; base += 1024) {
        int i = base + threadIdx.x;
        int v = (i < NN) ? g_deg[i] : 0;
        sh[threadIdx.x] = v;
        __syncthreads();
        for (int s = 1; s < 1024; s <<= 1) {
            int t = (threadIdx.x >= s) ? sh[threadIdx.x - s] : 0;
            __syncthreads();
            sh[threadIdx.x] += t;
            __syncthreads();
        }
        if (i < NN) g_off[i] = carry + sh[threadIdx.x] - v;
        __syncthreads();
        if (threadIdx.x == 1023) carry += sh[1023];
        __syncthreads();
    }
    if (threadIdx.x == 0) g_off[NN] = NE;
}

__global__ void k_scatter(const int* __restrict__ ei) {
    int e = blockIdx.x * 256 + threadIdx.x;
    int d = ei[NE + e];
    int p = atomicAdd(&g_cur[d], 1);
    g_csr[g_off[d] + p] = e;
}

// ---------------- edge logits: silu((q_s + q_d + ef@Wa1tail)) @ Wa2 ----------------
__global__ __launch_bounds__(256) void k_logits(
    const float* __restrict__ ef, const int* __restrict__ ei,
    const float* __restrict__ Wa1, const float* __restrict__ Wa2) {
    extern __shared__ float sm[];
    float* s_ef = sm;              // 256 * 65
    float* s_w = sm + 256 * 65;    // 64 * 32 (Wa1 rows 70..133)
    float* s_w2 = s_w + 2048;      // 32 * 8
    int tid = threadIdx.x;
    int e0 = blockIdx.x * 256;
    const float4* ef4 = (const float4*)(ef + (size_t)e0 * 64);
    for (int idx = tid; idx < 256 * 16; idx += 256) {
        int r = idx >> 4, c4 = idx & 15;
        float4 v = ef4[idx];
        float* dp = s_ef + r * 65 + c4 * 4;
        dp[0] = v.x; dp[1] = v.y; dp[2] = v.z; dp[3] = v.w;
    }
    for (int idx = tid; idx < 2048; idx += 256) s_w[idx] = Wa1[2240 + idx];
    if (tid < 256) s_w2[tid] = Wa2[tid];
    __syncthreads();

    int e = e0 + tid;
    int s = ei[e], d = ei[NE + e];
    unsigned long long acc[16];
    const float4* qs4 = (const float4*)(g_q + s * 64);
    const float4* qd4 = (const float4*)(g_q + d * 64 + 32);
#pragma unroll
    for (int i = 0; i < 8; i++) {
        float4 a = qs4[i], b = qd4[i];
        acc[2 * i] = pack2(a.x + b.x, a.y + b.y);
        acc[2 * i + 1] = pack2(a.z + b.z, a.w + b.w);
    }
    const float* efr = s_ef + tid * 65;
#pragma unroll 4
    for (int k = 0; k < 64; k++) {
        unsigned long long a2 = dup2(efr[k]);
        const unsigned long long* w = (const unsigned long long*)(s_w + k * 32);
#pragma unroll
        for (int j = 0; j < 16; j++) ffma2(acc[j], a2, w[j]);
    }
    float lg[8] = {0, 0, 0, 0, 0, 0, 0, 0};
#pragma unroll
    for (int j = 0; j < 16; j++) {
        float x0, x1;
        unpack2(acc[j], x0, x1);
        float s0 = silu_f(x0), s1 = silu_f(x1);
        const float* wr = s_w2 + (2 * j) * 8;
#pragma unroll
        for (int h = 0; h < 8; h++) lg[h] += s0 * wr[h] + s1 * wr[8 + h];
    }
    float4* lo = (float4*)(g_logits + (size_t)e * 8);
    lo[0] = make_float4(lg[0], lg[1], lg[2], lg[3]);
    lo[1] = make_float4(lg[4], lg[5], lg[6], lg[7]);
}

// ---------------- per-dst softmax + aggregation (warp per dst) ----------------
__global__ __launch_bounds__(256) void k_agg(const int* __restrict__ ei) {
    int lane = threadIdx.x & 31;
    int n = blockIdx.x * 8 + (threadIdx.x >> 5);
    int st = g_off[n], en = g_off[n + 1];
    int hl = (lane >> 1) & 7;  // head index — invariant across this lane's float4 slots
    float m = -1e30f;
    for (int i = st; i < en; i++) {
        int e = g_csr[i];
        m = fmaxf(m, g_logits[e * 8 + hl]);
    }
    float z = 0.f;
    for (int i = st; i < en; i++) {
        int e = g_csr[i];
        z += __expf(g_logits[e * 8 + hl] - m);
    }
    float rz = 1.f / (z + 1e-9f);
    float4 a0 = make_float4(0, 0, 0, 0), a1 = a0, a2 = a0, a3 = a0, a4 = a0;
    for (int i = st; i < en; i++) {
        int e = g_csr[i];
        int s = ei[e];
        float w = __expf(g_logits[e * 8 + hl] - m) * rz;
        const float4* vb = (const float4*)(g_v + s * 576);
        float4 v;
        v = vb[lane];        a0.x += w * v.x; a0.y += w * v.y; a0.z += w * v.z; a0.w += w * v.w;
        v = vb[32 + lane];   a1.x += w * v.x; a1.y += w * v.y; a1.z += w * v.z; a1.w += w * v.w;
        v = vb[64 + lane];   a2.x += w * v.x; a2.y += w * v.y; a2.z += w * v.z; a2.w += w * v.w;
        v = vb[96 + lane];   a3.x += w * v.x; a3.y += w * v.y; a3.z += w * v.z; a3.w += w * v.w;
        if (lane < 16) {
            v = vb[128 + lane]; a4.x += w * v.x; a4.y += w * v.y; a4.z += w * v.z; a4.w += w * v.w;
        }
    }
    float4* ag = (float4*)(g_agg + n * 576);
    ag[lane] = a0; ag[32 + lane] = a1; ag[64 + lane] = a2; ag[96 + lane] = a3;
    if (lane < 16) ag[128 + lane] = a4;
}

// ---------------- node output MLP + p precompute (warp per node) ----------------
__global__ __launch_bounds__(256) void k_node_out(
    const float* __restrict__ Wo, const float* __restrict__ W1,
    const float* __restrict__ W2, const float* __restrict__ We1,
    float* __restrict__ out_node) {
    __shared__ float sWo[64 * 32], sW1[32 * 32], sW2[32 * 32], sWe[64 * 32];
    int tid = threadIdx.x;
    for (int i = tid; i < 2048; i += 256) { sWo[i] = Wo[i]; sWe[i] = We1[i]; }
    for (int i = tid; i < 1024; i += 256) { sW1[i] = W1[i]; sW2[i] = W2[i]; }
    __syncthreads();
    int lane = tid & 31;
    int n = blockIdx.x * 8 + (tid >> 5);
    const float* ag = g_agg + n * 576;
    float ao[9], hr[9];
#pragma unroll
    for (int c = 0; c < 9; c++) {
        float r0 = ag[c * 64 + lane], r1 = ag[c * 64 + 32 + lane];
        float acc = 0.f;
#pragma unroll
        for (int j = 0; j < 32; j++) acc += __shfl_sync(FULLM, r0, j) * sWo[j * 32 + lane];
#pragma unroll
        for (int j = 0; j < 32; j++) acc += __shfl_sync(FULLM, r1, j) * sWo[(32 + j) * 32 + lane];
        ao[c] = acc;
    }
#pragma unroll
    for (int c = 0; c < 9; c++) {
        float acc = 0.f;
#pragma unroll
        for (int o = 0; o < 32; o++) acc += __shfl_sync(FULLM, ao[c], o) * sW1[o * 32 + lane];
        hr[c] = acc;
    }
    float gate = silu_f(hr[0]);
    float nn0 = 0.f;
#pragma unroll
    for (int c = 0; c < 9; c++) {
        float t = hr[c] * gate;
        float acc = ao[c];
#pragma unroll
        for (int o = 0; o < 32; o++) acc += __shfl_sync(FULLM, t, o) * sW2[o * 32 + lane];
        out_node[n * 288 + c * 32 + lane] = acc;
        if (c == 0) nn0 = acc;
    }
    float ps = 0.f, pd = 0.f;
#pragma unroll
    for (int k = 0; k < 32; k++) {
        float u = __shfl_sync(FULLM, nn0, k);
        ps += u * sWe[k * 32 + lane];
        pd += u * sWe[(32 + k) * 32 + lane];
    }
    g_p[n * 64 + lane] = ps;
    g_p[n * 64 + 32 + lane] = pd;
}

// ---------------- edge output MLP ----------------
__global__ __launch_bounds__(256) void k_edge_out(
    const float* __restrict__ ef, const int* __restrict__ ei,
    const float* __restrict__ We1, const float* __restrict__ We2,
    float* __restrict__ out_edge) {
    extern __shared__ float sm[];
    float* s_ef = sm;               // 256 * 65
    float* s_w1 = sm + 256 * 65;    // We1 rows 64..127 (64x32)
    float* s_w2 = s_w1 + 2048;      // We2 (32x64)
    int tid = threadIdx.x;
    int e0 = blockIdx.x * 256;
    const float4* ef4 = (const float4*)(ef + (size_t)e0 * 64);
    for (int idx = tid; idx < 256 * 16; idx += 256) {
        int r = idx >> 4, c4 = idx & 15;
        float4 v = ef4[idx];
        float* dp = s_ef + r * 65 + c4 * 4;
        dp[0] = v.x; dp[1] = v.y; dp[2] = v.z; dp[3] = v.w;
    }
    for (int idx = tid; idx < 2048; idx += 256) { s_w1[idx] = We1[2048 + idx]; s_w2[idx] = We2[idx]; }
    __syncthreads();

    int e = e0 + tid;
    int s = ei[e], d = ei[NE + e];
    unsigned long long acc[16];
    const float4* ps4 = (const float4*)(g_p + s * 64);
    const float4* pd4 = (const float4*)(g_p + d * 64 + 32);
#pragma unroll
    for (int i = 0; i < 8; i++) {
        float4 a = ps4[i], b = pd4[i];
        acc[2 * i] = pack2(a.x + b.x, a.y + b.y);
        acc[2 * i + 1] = pack2(a.z + b.z, a.w + b.w);
    }
    const float* efr = s_ef + tid * 65;
#pragma unroll 4
    for (int k = 0; k < 64; k++) {
        unsigned long long a2 = dup2(efr[k]);
        const unsigned long long* w = (const unsigned long long*)(s_w1 + k * 32);
#pragma unroll
        for (int j = 0; j < 16; j++) ffma2(acc[j], a2, w[j]);
    }
    float sv[32];
#pragma unroll
    for (int j = 0; j < 16; j++) {
        float x0, x1;
        unpack2(acc[j], x0, x1);
        sv[2 * j] = silu_f(x0);
        sv[2 * j + 1] = silu_f(x1);
    }
#pragma unroll
    for (int half = 0; half < 2; half++) {
        unsigned long long o2[16];
#pragma unroll
        for (int t = 0; t < 16; t++) o2[t] = 0ull;
#pragma unroll 4
        for (int j = 0; j < 32; j++) {
            unsigned long long a2 = dup2(sv[j]);
            const unsigned long long* w = (const unsigned long long*)(s_w2 + j * 64 + half * 32);
#pragma unroll
            for (int t = 0; t < 16; t++) ffma2(o2[t], a2, w[t]);
        }
        const float* efo = s_ef + tid * 65 + half * 32;
        float4* dp = (float4*)(out_edge + (size_t)e * 64 + half * 32);
#pragma unroll
        for (int t = 0; t < 8; t++) {
            float x0, x1, x2, x3;
            unpack2(o2[2 * t], x0, x1);
            unpack2(o2[2 * t + 1], x2, x3);
            dp[t] = make_float4(x0 + efo[4 * t], x1 + efo[4 * t + 1],
                                x2 + efo[4 * t + 2], x3 + efo[4 * t + 3]);
        }
    }
}

// ---------------- launch ----------------
extern "C" void kernel_launch(void* const* d_in, const int* in_sizes, int n_in,
                              void* d_out, int out_size) {
    const float* bb_emb = (const float*)d_in[0];
    const float* bb_rel = (const float*)d_in[1];
    const float* ef = (const float*)d_in[2];
    const int* ei = (const int*)d_in[3];
    const void* mask = d_in[4];
    const float* Wa1 = (const float*)d_in[5];
    const float* Wa2 = (const float*)d_in[6];
    const float* Wv = (const float*)d_in[7];
    const float* Wo = (const float*)d_in[8];
    const float* W1 = (const float*)d_in[9];
    const float* W2 = (const float*)d_in[10];
    const float* We1 = (const float*)d_in[11];
    const float* We2 = (const float*)d_in[12];
    float* out_node = (float*)d_out;
    float* out_edge = out_node + (size_t)NN * 288;

    const int SMEM_LG = (256 * 65 + 64 * 32 + 32 * 8) * 4;   // 75776
    const int SMEM_EO = (256 * 65 + 64 * 32 + 32 * 64) * 4;  // 82944
    cudaFuncSetAttribute((const void*)k_logits, cudaFuncAttributeMaxDynamicSharedMemorySize, SMEM_LG);
    cudaFuncSetAttribute((const void*)k_edge_out, cudaFuncAttributeMaxDynamicSharedMemorySize, SMEM_EO);

    k_mask_detect<<<1, 256>>>(mask);
    k_mask_conv<<<(NN + 255) / 256, 256>>>(mask);
    k_init<<<(NN + 255) / 256, 256>>>();
    k_node_prep<<<1250, 256>>>(bb_emb, bb_rel, Wa1, Wv);
    k_count<<<1250, 256>>>(ei);
    k_scan<<<1, 1024>>>();
    k_scatter<<<1250, 256>>>(ei);
    k_logits<<<1250, 256, SMEM_LG>>>(ef, ei, Wa1, Wa2);
    k_agg<<<1250, 256>>>(ei);
    k_node_out<<<1250, 256>>>(Wo, W1, W2, We1, out_node);
    k_edge_out<<<1250, 256, SMEM_EO>>>(ef, ei, We1, We2, out_edge);
}

// round 3
// speedup vs baseline: 1.0811x; 1.0811x over previous
#include <cuda_runtime.h>

#define NN 10000
#define NE 320000
#define FULLM 0xffffffffu

// ---------------- scratch (static device memory; no allocation) ----------------
__device__ __align__(16) float g_q[NN * 64];        // q_src | q_dst per node
__device__ __align__(16) float g_v[NN * 576];       // v_nodes [N][9*64]
__device__ __align__(16) float g_wexp[NE * 8];      // exp(logit), CSR-slot order
__device__ __align__(16) float g_p[NN * 64];        // p_src | p_dst per node
__device__ float g_maskf[NN];
__device__ int g_deg[NN];
__device__ int g_cur[NN];
__device__ int g_off[NN + 1];
__device__ int g_pos[NE];                           // edge -> CSR slot
__device__ int g_srcp[NE];                          // CSR slot -> src node

// ---------------- f32x2 helpers ----------------
static __device__ __forceinline__ unsigned long long pack2(float x, float y) {
    unsigned long long r; asm("mov.b64 %0, {%1,%2};" : "=l"(r) : "f"(x), "f"(y)); return r;
}
static __device__ __forceinline__ unsigned long long dup2(float x) {
    unsigned long long r; asm("mov.b64 %0, {%1,%1};" : "=l"(r) : "f"(x)); return r;
}
static __device__ __forceinline__ void unpack2(unsigned long long v, float& x, float& y) {
    asm("mov.b64 {%0,%1}, %2;" : "=f"(x), "=f"(y) : "l"(v));
}
static __device__ __forceinline__ void ffma2(unsigned long long& d, unsigned long long a, unsigned long long b) {
    asm("fma.rn.f32x2 %0, %1, %2, %0;" : "+l"(d) : "l"(a), "l"(b));
}
static __device__ __forceinline__ float silu_f(float x) { return x / (1.f + __expf(-x)); }

// ---------------- mask dtype detection + conversion (single block) ----------------
__global__ void k_mask(const void* __restrict__ p) {
    const unsigned* u = (const unsigned*)p;
    __shared__ int okf, oki;
    if (threadIdx.x == 0) { okf = 1; oki = 1; }
    __syncthreads();
    for (int i = threadIdx.x; i < 2500; i += 1024) {
        unsigned v = u[i];
        if (!(v == 0u || v == 0x3F800000u)) okf = 0;
        if (!(v == 0u || v == 1u)) oki = 0;
    }
    __syncthreads();
    int t = okf ? 0 : (oki ? 1 : 2);
    for (int i = threadIdx.x; i < NN; i += 1024) {
        float m;
        if (t == 0) m = ((const float*)p)[i];
        else if (t == 1) m = (float)(((const int*)p)[i] != 0);
        else m = ((const unsigned char*)p)[i] ? 1.f : 0.f;
        g_maskf[i] = m;
    }
}

// ---------------- node prep: q halves + v = node@Wv, FFMA2 paired outputs ----------------
__global__ __launch_bounds__(256) void k_node_prep(
    const float* __restrict__ bb_emb, const float* __restrict__ bb_rel,
    const float* __restrict__ Wa1, const float* __restrict__ Wv) {
    __shared__ unsigned long long sWvP[35 * 32];  // {Wv[k,lane], Wv[k,32+lane]}
    __shared__ unsigned long long sWaP[35 * 32];  // {Wa1[k,lane], Wa1[35+k,lane]}
    int tid = threadIdx.x;
    for (int i = tid; i < 35 * 32; i += 256) {
        int k = i >> 5, j = i & 31;
        ((float2*)sWvP)[i] = make_float2(Wv[k * 64 + j], Wv[k * 64 + 32 + j]);
        ((float2*)sWaP)[i] = make_float2(Wa1[k * 32 + j], Wa1[(k + 35) * 32 + j]);
    }
    __syncthreads();
    int lane = tid & 31;
    int n = blockIdx.x * 8 + (tid >> 5);
    float mk = g_maskf[n];

    // q_src / q_dst
    float r0 = bb_emb[n * 288 + lane];
    unsigned long long accq = 0ull;
#pragma unroll
    for (int k = 0; k < 32; k++)
        ffma2(accq, dup2(__shfl_sync(FULLM, r0, k)), sWaP[k * 32 + lane]);
    ffma2(accq, dup2(mk), sWaP[34 * 32 + lane]);
    float qs, qd; unpack2(accq, qs, qd);
    g_q[n * 64 + lane] = qs;
    g_q[n * 64 + 32 + lane] = qd;

    // v_nodes
#pragma unroll
    for (int c = 0; c < 9; c++) {
        float f = bb_emb[n * 288 + c * 32 + lane];
        unsigned long long acc = 0ull;
        if (c == 0) {
            ffma2(acc, dup2(mk), sWvP[34 * 32 + lane]);
        } else if (c <= 3) {
#pragma unroll
            for (int b = 0; b < 3; b++)
                ffma2(acc, dup2(bb_rel[n * 9 + b * 3 + (c - 1)]), sWvP[(32 + b) * 32 + lane]);
        }
#pragma unroll
        for (int k = 0; k < 32; k++)
            ffma2(acc, dup2(__shfl_sync(FULLM, f, k)), sWvP[k * 32 + lane]);
        float a0, a1; unpack2(acc, a0, a1);
        g_v[n * 576 + c * 64 + lane] = a0;
        g_v[n * 576 + c * 64 + 32 + lane] = a1;
    }
}

// ---------------- CSR build ----------------
__global__ void k_count(const int* __restrict__ ei) {
    int e = blockIdx.x * 256 + threadIdx.x;
    atomicAdd(&g_deg[ei[NE + e]], 1);
}

// warp-shuffle scan; also resets g_deg/g_cur for this (and the next) run
__global__ void k_scan() {
    __shared__ int wsum[32];
    __shared__ int carry;
    int tid = threadIdx.x, lane = tid & 31, wid = tid >> 5;
    if (tid == 0) carry = 0;
    __syncthreads();
    for (int base = 0; base < NN; base += 1024) {
        int i = base + tid;
        int v = (i < NN) ? g_deg[i] : 0;
        int x = v;
#pragma unroll
        for (int s = 1; s < 32; s <<= 1) { int t = __shfl_up_sync(FULLM, x, s); if (lane >= s) x += t; }
        if (lane == 31) wsum[wid] = x;
        __syncthreads();
        if (wid == 0) {
            int y = wsum[lane];
#pragma unroll
            for (int s = 1; s < 32; s <<= 1) { int t = __shfl_up_sync(FULLM, y, s); if (lane >= s) y += t; }
            wsum[lane] = y;
        }
        __syncthreads();
        int prefix = carry + (wid ? wsum[wid - 1] : 0);
        if (i < NN) { g_off[i] = prefix + x - v; g_deg[i] = 0; g_cur[i] = 0; }
        __syncthreads();
        if (tid == 0) carry += wsum[31];
        __syncthreads();
    }
    if (tid == 0) g_off[NN] = NE;
}

__global__ void k_scatter(const int* __restrict__ ei) {
    int e = blockIdx.x * 256 + threadIdx.x;
    int d = ei[NE + e];
    int p = atomicAdd(&g_cur[d], 1);
    g_pos[e] = g_off[d] + p;
}

// ---------------- edge logits -> exp, written in CSR-slot order ----------------
__global__ __launch_bounds__(256) void k_logits(
    const float* __restrict__ ef, const int* __restrict__ ei,
    const float* __restrict__ Wa1, const float* __restrict__ Wa2) {
    extern __shared__ float sm[];
    float* s_ef = sm;              // 256 * 65
    float* s_w = sm + 256 * 65;    // 64 * 32 (Wa1 rows 70..133)
    float* s_w2 = s_w + 2048;      // 32 * 8
    int tid = threadIdx.x;
    int e0 = blockIdx.x * 256;
    const float4* ef4 = (const float4*)(ef + (size_t)e0 * 64);
    for (int idx = tid; idx < 256 * 16; idx += 256) {
        int r = idx >> 4, c4 = idx & 15;
        float4 v = ef4[idx];
        float* dp = s_ef + r * 65 + c4 * 4;
        dp[0] = v.x; dp[1] = v.y; dp[2] = v.z; dp[3] = v.w;
    }
    for (int idx = tid; idx < 2048; idx += 256) s_w[idx] = Wa1[2240 + idx];
    if (tid < 256) s_w2[tid] = Wa2[tid];
    __syncthreads();

    int e = e0 + tid;
    int s = ei[e], d = ei[NE + e];
    unsigned long long acc[16];
    const float4* qs4 = (const float4*)(g_q + s * 64);
    const float4* qd4 = (const float4*)(g_q + d * 64 + 32);
#pragma unroll
    for (int i = 0; i < 8; i++) {
        float4 a = qs4[i], b = qd4[i];
        acc[2 * i] = pack2(a.x + b.x, a.y + b.y);
        acc[2 * i + 1] = pack2(a.z + b.z, a.w + b.w);
    }
    const float* efr = s_ef + tid * 65;
#pragma unroll 4
    for (int k = 0; k < 64; k++) {
        unsigned long long a2 = dup2(efr[k]);
        const unsigned long long* w = (const unsigned long long*)(s_w + k * 32);
#pragma unroll
        for (int j = 0; j < 16; j++) ffma2(acc[j], a2, w[j]);
    }
    float lg[8] = {0, 0, 0, 0, 0, 0, 0, 0};
#pragma unroll
    for (int j = 0; j < 16; j++) {
        float x0, x1;
        unpack2(acc[j], x0, x1);
        float s0 = silu_f(x0), s1 = silu_f(x1);
        const float* wr = s_w2 + (2 * j) * 8;
#pragma unroll
        for (int h = 0; h < 8; h++) lg[h] += s0 * wr[h] + s1 * wr[8 + h];
    }
    int pos = g_pos[e];
    g_srcp[pos] = s;
    float4* lo = (float4*)(g_wexp + (size_t)pos * 8);
    lo[0] = make_float4(__expf(lg[0]), __expf(lg[1]), __expf(lg[2]), __expf(lg[3]));
    lo[1] = make_float4(__expf(lg[4]), __expf(lg[5]), __expf(lg[6]), __expf(lg[7]));
}

// ---------------- fused: single-pass softmax-agg + node output MLP + p precompute ----------------
__global__ __launch_bounds__(256) void k_agg_node(
    const float* __restrict__ Wo, const float* __restrict__ W1,
    const float* __restrict__ W2, const float* __restrict__ We1,
    float* __restrict__ out_node) {
    __shared__ float2 sWoP[32 * 32];   // {Wo[2jp,lane], Wo[2jp+1,lane]}
    __shared__ float sW1[1024], sW2[1024], sWe[2048];
    __shared__ float sAgg[8 * 576];
    int tid = threadIdx.x;
    for (int i = tid; i < 1024; i += 256) {
        int jp = i >> 5, l = i & 31;
        sWoP[i] = make_float2(Wo[(2 * jp) * 32 + l], Wo[(2 * jp + 1) * 32 + l]);
        sW1[i] = W1[i]; sW2[i] = W2[i];
    }
    for (int i = tid; i < 2048; i += 256) sWe[i] = We1[i];
    __syncthreads();
    int lane = tid & 31, wid = tid >> 5;
    int n = blockIdx.x * 8 + wid;
    int st = g_off[n], en = g_off[n + 1];
    int hl = (lane >> 1) & 7;
    float z = 0.f;
    float4 a0 = make_float4(0, 0, 0, 0), a1 = a0, a2 = a0, a3 = a0, a4 = a0;
#pragma unroll 2
    for (int i = st; i < en; i++) {
        int s = g_srcp[i];
        float w = g_wexp[(size_t)i * 8 + hl];
        z += w;
        const float4* vb = (const float4*)(g_v + s * 576);
        float4 v;
        v = vb[lane];        a0.x += w * v.x; a0.y += w * v.y; a0.z += w * v.z; a0.w += w * v.w;
        v = vb[32 + lane];   a1.x += w * v.x; a1.y += w * v.y; a1.z += w * v.z; a1.w += w * v.w;
        v = vb[64 + lane];   a2.x += w * v.x; a2.y += w * v.y; a2.z += w * v.z; a2.w += w * v.w;
        v = vb[96 + lane];   a3.x += w * v.x; a3.y += w * v.y; a3.z += w * v.z; a3.w += w * v.w;
        if (lane < 16) {
            v = vb[128 + lane]; a4.x += w * v.x; a4.y += w * v.y; a4.z += w * v.z; a4.w += w * v.w;
        }
    }
    float rz = 1.f / (z + 1e-9f);
    a0.x *= rz; a0.y *= rz; a0.z *= rz; a0.w *= rz;
    a1.x *= rz; a1.y *= rz; a1.z *= rz; a1.w *= rz;
    a2.x *= rz; a2.y *= rz; a2.z *= rz; a2.w *= rz;
    a3.x *= rz; a3.y *= rz; a3.z *= rz; a3.w *= rz;
    a4.x *= rz; a4.y *= rz; a4.z *= rz; a4.w *= rz;
    float* sa = sAgg + wid * 576;
    ((float4*)sa)[lane] = a0; ((float4*)sa)[32 + lane] = a1;
    ((float4*)sa)[64 + lane] = a2; ((float4*)sa)[96 + lane] = a3;
    if (lane < 16) ((float4*)sa)[128 + lane] = a4;
    __syncwarp();

    // attn_out = agg @ Wo  (paired LDS.64 broadcasts + FFMA2)
    float ao[9];
#pragma unroll
    for (int c = 0; c < 9; c++) {
        unsigned long long acc2 = 0ull;
        const unsigned long long* sav = (const unsigned long long*)(sa + c * 64);
#pragma unroll
        for (int jp = 0; jp < 32; jp++)
            ffma2(acc2, sav[jp], *(const unsigned long long*)&sWoP[jp * 32 + lane]);
        float x0, x1; unpack2(acc2, x0, x1);
        ao[c] = x0 + x1;
    }
    // h = ao @ W1
    float hr[9];
#pragma unroll
    for (int c = 0; c < 9; c++) {
        float acc = 0.f;
#pragma unroll
        for (int o = 0; o < 32; o++) acc += __shfl_sync(FULLM, ao[c], o) * sW1[o * 32 + lane];
        hr[c] = acc;
    }
    float gate = silu_f(hr[0]);
    float nn0 = 0.f;
#pragma unroll
    for (int c = 0; c < 9; c++) {
        float t = hr[c] * gate;
        float acc = ao[c];
#pragma unroll
        for (int o = 0; o < 32; o++) acc += __shfl_sync(FULLM, t, o) * sW2[o * 32 + lane];
        out_node[n * 288 + c * 32 + lane] = acc;
        if (c == 0) nn0 = acc;
    }
    float ps = 0.f, pd = 0.f;
#pragma unroll
    for (int k = 0; k < 32; k++) {
        float u = __shfl_sync(FULLM, nn0, k);
        ps += u * sWe[k * 32 + lane];
        pd += u * sWe[(32 + k) * 32 + lane];
    }
    g_p[n * 64 + lane] = ps;
    g_p[n * 64 + 32 + lane] = pd;
}

// ---------------- edge output MLP ----------------
__global__ __launch_bounds__(256) void k_edge_out(
    const float* __restrict__ ef, const int* __restrict__ ei,
    const float* __restrict__ We1, const float* __restrict__ We2,
    float* __restrict__ out_edge) {
    extern __shared__ float sm[];
    float* s_ef = sm;               // 256 * 65
    float* s_w1 = sm + 256 * 65;    // We1 rows 64..127 (64x32)
    float* s_w2 = s_w1 + 2048;      // We2 (32x64)
    int tid = threadIdx.x;
    int e0 = blockIdx.x * 256;
    const float4* ef4 = (const float4*)(ef + (size_t)e0 * 64);
    for (int idx = tid; idx < 256 * 16; idx += 256) {
        int r = idx >> 4, c4 = idx & 15;
        float4 v = ef4[idx];
        float* dp = s_ef + r * 65 + c4 * 4;
        dp[0] = v.x; dp[1] = v.y; dp[2] = v.z; dp[3] = v.w;
    }
    for (int idx = tid; idx < 2048; idx += 256) { s_w1[idx] = We1[2048 + idx]; s_w2[idx] = We2[idx]; }
    __syncthreads();

    int e = e0 + tid;
    int s = ei[e], d = ei[NE + e];
    unsigned long long acc[16];
    const float4* ps4 = (const float4*)(g_p + s * 64);
    const float4* pd4 = (const float4*)(g_p + d * 64 + 32);
#pragma unroll
    for (int i = 0; i < 8; i++) {
        float4 a = ps4[i], b = pd4[i];
        acc[2 * i] = pack2(a.x + b.x, a.y + b.y);
        acc[2 * i + 1] = pack2(a.z + b.z, a.w + b.w);
    }
    const float* efr = s_ef + tid * 65;
#pragma unroll 4
    for (int k = 0; k < 64; k++) {
        unsigned long long a2 = dup2(efr[k]);
        const unsigned long long* w = (const unsigned long long*)(s_w1 + k * 32);
#pragma unroll
        for (int j = 0; j < 16; j++) ffma2(acc[j], a2, w[j]);
    }
    float sv[32];
#pragma unroll
    for (int j = 0; j < 16; j++) {
        float x0, x1;
        unpack2(acc[j], x0, x1);
        sv[2 * j] = silu_f(x0);
        sv[2 * j + 1] = silu_f(x1);
    }
#pragma unroll
    for (int half = 0; half < 2; half++) {
        unsigned long long o2[16];
#pragma unroll
        for (int t = 0; t < 16; t++) o2[t] = 0ull;
#pragma unroll 4
        for (int j = 0; j < 32; j++) {
            unsigned long long a2 = dup2(sv[j]);
            const unsigned long long* w = (const unsigned long long*)(s_w2 + j * 64 + half * 32);
#pragma unroll
            for (int t = 0; t < 16; t++) ffma2(o2[t], a2, w[t]);
        }
        const float* efo = s_ef + tid * 65 + half * 32;
        float4* dp = (float4*)(out_edge + (size_t)e * 64 + half * 32);
#pragma unroll
        for (int t = 0; t < 8; t++) {
            float x0, x1, x2, x3;
            unpack2(o2[2 * t], x0, x1);
            unpack2(o2[2 * t + 1], x2, x3);
            dp[t] = make_float4(x0 + efo[4 * t], x1 + efo[4 * t + 1],
                                x2 + efo[4 * t + 2], x3 + efo[4 * t + 3]);
        }
    }
}

// ---------------- launch ----------------
extern "C" void kernel_launch(void* const* d_in, const int* in_sizes, int n_in,
                              void* d_out, int out_size) {
    const float* bb_emb = (const float*)d_in[0];
    const float* bb_rel = (const float*)d_in[1];
    const float* ef = (const float*)d_in[2];
    const int* ei = (const int*)d_in[3];
    const void* mask = d_in[4];
    const float* Wa1 = (const float*)d_in[5];
    const float* Wa2 = (const float*)d_in[6];
    const float* Wv = (const float*)d_in[7];
    const float* Wo = (const float*)d_in[8];
    const float* W1 = (const float*)d_in[9];
    const float* W2 = (const float*)d_in[10];
    const float* We1 = (const float*)d_in[11];
    const float* We2 = (const float*)d_in[12];
    float* out_node = (float*)d_out;
    float* out_edge = out_node + (size_t)NN * 288;

    const int SMEM_LG = (256 * 65 + 64 * 32 + 32 * 8) * 4;   // 75776
    const int SMEM_EO = (256 * 65 + 64 * 32 + 32 * 64) * 4;  // 82944
    cudaFuncSetAttribute((const void*)k_logits, cudaFuncAttributeMaxDynamicSharedMemorySize, SMEM_LG);
    cudaFuncSetAttribute((const void*)k_edge_out, cudaFuncAttributeMaxDynamicSharedMemorySize, SMEM_EO);

    k_mask<<<1, 1024>>>(mask);
    k_count<<<1250, 256>>>(ei);
    k_scan<<<1, 1024>>>();
    k_scatter<<<1250, 256>>>(ei);
    k_node_prep<<<1250, 256>>>(bb_emb, bb_rel, Wa1, Wv);
    k_logits<<<1250, 256, SMEM_LG>>>(ef, ei, Wa1, Wa2);
    k_agg_node<<<1250, 256>>>(Wo, W1, W2, We1, out_node);
    k_edge_out<<<1250, 256, SMEM_EO>>>(ef, ei, We1, We2, out_edge);
}

// round 4
// speedup vs baseline: 1.2664x; 1.1714x over previous
#include <cuda_runtime.h>

#define NN 10000
#define NE 320000
#define FULLM 0xffffffffu

// ---------------- scratch (static device memory; no allocation) ----------------
__device__ __align__(16) float g_q[NN * 64];        // q_src | q_dst per node
__device__ __align__(16) float g_v[NN * 576];       // v_nodes [N][9*64]
__device__ __align__(16) float g_wexp[NE * 8];      // exp(logit), CSR-slot order
__device__ __align__(16) float g_p[NN * 64];        // p_src | p_dst per node
__device__ float g_maskf[NN];
__device__ int g_deg[NN];
__device__ int g_cur[NN];
__device__ int g_off[NN + 1];
__device__ int g_srcp[NE];                          // CSR slot -> src node

// ---------------- f32x2 helpers ----------------
static __device__ __forceinline__ unsigned long long pack2(float x, float y) {
    unsigned long long r; asm("mov.b64 %0, {%1,%2};" : "=l"(r) : "f"(x), "f"(y)); return r;
}
static __device__ __forceinline__ unsigned long long dup2(float x) {
    unsigned long long r; asm("mov.b64 %0, {%1,%1};" : "=l"(r) : "f"(x)); return r;
}
static __device__ __forceinline__ void unpack2(unsigned long long v, float& x, float& y) {
    asm("mov.b64 {%0,%1}, %2;" : "=f"(x), "=f"(y) : "l"(v));
}
static __device__ __forceinline__ void ffma2(unsigned long long& d, unsigned long long a, unsigned long long b) {
    asm("fma.rn.f32x2 %0, %1, %2, %0;" : "+l"(d) : "l"(a), "l"(b));
}
static __device__ __forceinline__ float silu_f(float x) { return x / (1.f + __expf(-x)); }

// ---------------- fused: mask dtype conversion (block 0) + degree count (all) ----------------
__global__ void k_mask_count(const void* __restrict__ p, const int* __restrict__ ei) {
    int e = blockIdx.x * 256 + threadIdx.x;
    atomicAdd(&g_deg[ei[NE + e]], 1);
    if (blockIdx.x == 0) {
        const unsigned* u = (const unsigned*)p;
        __shared__ int okf, oki;
        if (threadIdx.x == 0) { okf = 1; oki = 1; }
        __syncthreads();
        for (int i = threadIdx.x; i < 2500; i += 256) {
            unsigned v = u[i];
            if (!(v == 0u || v == 0x3F800000u)) okf = 0;
            if (!(v == 0u || v == 1u)) oki = 0;
        }
        __syncthreads();
        int t = okf ? 0 : (oki ? 1 : 2);
        for (int i = threadIdx.x; i < NN; i += 256) {
            float m;
            if (t == 0) m = ((const float*)p)[i];
            else if (t == 1) m = (float)(((const int*)p)[i] != 0);
            else m = ((const unsigned char*)p)[i] ? 1.f : 0.f;
            g_maskf[i] = m;
        }
    }
}

// ---------------- warp-shuffle scan; resets g_deg/g_cur ----------------
__global__ void k_scan() {
    __shared__ int wsum[32];
    __shared__ int carry;
    int tid = threadIdx.x, lane = tid & 31, wid = tid >> 5;
    if (tid == 0) carry = 0;
    __syncthreads();
    for (int base = 0; base < NN; base += 1024) {
        int i = base + tid;
        int v = (i < NN) ? g_deg[i] : 0;
        int x = v;
#pragma unroll
        for (int s = 1; s < 32; s <<= 1) { int t = __shfl_up_sync(FULLM, x, s); if (lane >= s) x += t; }
        if (lane == 31) wsum[wid] = x;
        __syncthreads();
        if (wid == 0) {
            int y = wsum[lane];
#pragma unroll
            for (int s = 1; s < 32; s <<= 1) { int t = __shfl_up_sync(FULLM, y, s); if (lane >= s) y += t; }
            wsum[lane] = y;
        }
        __syncthreads();
        int prefix = carry + (wid ? wsum[wid - 1] : 0);
        if (i < NN) { g_off[i] = prefix + x - v; g_deg[i] = 0; g_cur[i] = 0; }
        __syncthreads();
        if (tid == 0) carry += wsum[31];
        __syncthreads();
    }
    if (tid == 0) g_off[NN] = NE;
}

// ---------------- node prep: q halves + v = node@Wv, FFMA2 paired outputs ----------------
__global__ __launch_bounds__(256) void k_node_prep(
    const float* __restrict__ bb_emb, const float* __restrict__ bb_rel,
    const float* __restrict__ Wa1, const float* __restrict__ Wv) {
    __shared__ unsigned long long sWvP[35 * 32];  // {Wv[k,lane], Wv[k,32+lane]}
    __shared__ unsigned long long sWaP[35 * 32];  // {Wa1[k,lane], Wa1[35+k,lane]}
    int tid = threadIdx.x;
    for (int i = tid; i < 35 * 32; i += 256) {
        int k = i >> 5, j = i & 31;
        ((float2*)sWvP)[i] = make_float2(Wv[k * 64 + j], Wv[k * 64 + 32 + j]);
        ((float2*)sWaP)[i] = make_float2(Wa1[k * 32 + j], Wa1[(k + 35) * 32 + j]);
    }
    __syncthreads();
    int lane = tid & 31;
    int n = blockIdx.x * 8 + (tid >> 5);
    float mk = g_maskf[n];

    float r0 = bb_emb[n * 288 + lane];
    unsigned long long accq = 0ull;
#pragma unroll
    for (int k = 0; k < 32; k++)
        ffma2(accq, dup2(__shfl_sync(FULLM, r0, k)), sWaP[k * 32 + lane]);
    ffma2(accq, dup2(mk), sWaP[34 * 32 + lane]);
    float qs, qd; unpack2(accq, qs, qd);
    g_q[n * 64 + lane] = qs;
    g_q[n * 64 + 32 + lane] = qd;

#pragma unroll
    for (int c = 0; c < 9; c++) {
        float f = bb_emb[n * 288 + c * 32 + lane];
        unsigned long long acc = 0ull;
        if (c == 0) {
            ffma2(acc, dup2(mk), sWvP[34 * 32 + lane]);
        } else if (c <= 3) {
#pragma unroll
            for (int b = 0; b < 3; b++)
                ffma2(acc, dup2(bb_rel[n * 9 + b * 3 + (c - 1)]), sWvP[(32 + b) * 32 + lane]);
        }
#pragma unroll
        for (int k = 0; k < 32; k++)
            ffma2(acc, dup2(__shfl_sync(FULLM, f, k)), sWvP[k * 32 + lane]);
        float a0, a1; unpack2(acc, a0, a1);
        g_v[n * 576 + c * 64 + lane] = a0;
        g_v[n * 576 + c * 64 + 32 + lane] = a1;
    }
}

// ---------------- edge logits (+fused scatter): two-phase ef staging ----------------
__global__ __launch_bounds__(256) void k_logits(
    const float* __restrict__ ef, const int* __restrict__ ei,
    const float* __restrict__ Wa1, const float* __restrict__ Wa2) {
    __shared__ float s_ef[256 * 33];
    __shared__ float s_w[2048];    // Wa1 rows 70..133
    __shared__ float s_w2[256];    // Wa2
    int tid = threadIdx.x;
    int e0 = blockIdx.x * 256;
    for (int i = tid; i < 2048; i += 256) s_w[i] = Wa1[2240 + i];
    s_w2[tid] = Wa2[tid];

    int e = e0 + tid;
    int s = ei[e], d = ei[NE + e];
    unsigned long long acc[16];
    {
        const float4* qs4 = (const float4*)(g_q + s * 64);
        const float4* qd4 = (const float4*)(g_q + d * 64 + 32);
#pragma unroll
        for (int i = 0; i < 8; i++) {
            float4 a = qs4[i], b = qd4[i];
            acc[2 * i] = pack2(a.x + b.x, a.y + b.y);
            acc[2 * i + 1] = pack2(a.z + b.z, a.w + b.w);
        }
    }
#pragma unroll
    for (int phase = 0; phase < 2; phase++) {
        __syncthreads();
        for (int i = tid; i < 2048; i += 256) {
            int r = i >> 3, c4 = i & 7;
            float4 v = *(const float4*)(ef + (size_t)(e0 + r) * 64 + phase * 32 + c4 * 4);
            float* dp = s_ef + r * 33 + c4 * 4;
            dp[0] = v.x; dp[1] = v.y; dp[2] = v.z; dp[3] = v.w;
        }
        __syncthreads();
        const float* efr = s_ef + tid * 33;
        const float* wb = s_w + phase * 32 * 32;
#pragma unroll 4
        for (int k = 0; k < 32; k++) {
            unsigned long long a2 = dup2(efr[k]);
            const unsigned long long* w = (const unsigned long long*)(wb + k * 32);
#pragma unroll
            for (int j = 0; j < 16; j++) ffma2(acc[j], a2, w[j]);
        }
    }
    float lg[8] = {0, 0, 0, 0, 0, 0, 0, 0};
#pragma unroll
    for (int j = 0; j < 16; j++) {
        float x0, x1;
        unpack2(acc[j], x0, x1);
        float s0 = silu_f(x0), s1 = silu_f(x1);
        const float* wr = s_w2 + (2 * j) * 8;
#pragma unroll
        for (int h = 0; h < 8; h++) lg[h] += s0 * wr[h] + s1 * wr[8 + h];
    }
    int pos = g_off[d] + atomicAdd(&g_cur[d], 1);
    g_srcp[pos] = s;
    float4* lo = (float4*)(g_wexp + (size_t)pos * 8);
    lo[0] = make_float4(__expf(lg[0]), __expf(lg[1]), __expf(lg[2]), __expf(lg[3]));
    lo[1] = make_float4(__expf(lg[4]), __expf(lg[5]), __expf(lg[6]), __expf(lg[7]));
}

// ---------------- fused: single-pass softmax-agg + node output MLP + p precompute ----------------
__global__ __launch_bounds__(256) void k_agg_node(
    const float* __restrict__ Wo, const float* __restrict__ W1,
    const float* __restrict__ W2, const float* __restrict__ We1,
    float* __restrict__ out_node) {
    __shared__ float2 sWoP[32 * 32];   // {Wo[2jp,lane], Wo[2jp+1,lane]}
    __shared__ float sW1[1024], sW2[1024], sWe[2048];
    __shared__ float sAgg[8 * 576];
    int tid = threadIdx.x;
    for (int i = tid; i < 1024; i += 256) {
        int jp = i >> 5, l = i & 31;
        sWoP[i] = make_float2(Wo[(2 * jp) * 32 + l], Wo[(2 * jp + 1) * 32 + l]);
        sW1[i] = W1[i]; sW2[i] = W2[i];
    }
    for (int i = tid; i < 2048; i += 256) sWe[i] = We1[i];
    __syncthreads();
    int lane = tid & 31, wid = tid >> 5;
    int n = blockIdx.x * 8 + wid;
    int st = g_off[n], en = g_off[n + 1];
    int hl = (lane >> 1) & 7;
    float z = 0.f;
    float4 a0 = make_float4(0, 0, 0, 0), a1 = a0, a2 = a0, a3 = a0, a4 = a0;
#pragma unroll 4
    for (int i = st; i < en; i++) {
        int s = __ldg(&g_srcp[i]);
        float w = __ldg(&g_wexp[(size_t)i * 8 + hl]);
        z += w;
        const float4* vb = (const float4*)(g_v + s * 576);
        float4 v;
        v = vb[lane];        a0.x += w * v.x; a0.y += w * v.y; a0.z += w * v.z; a0.w += w * v.w;
        v = vb[32 + lane];   a1.x += w * v.x; a1.y += w * v.y; a1.z += w * v.z; a1.w += w * v.w;
        v = vb[64 + lane];   a2.x += w * v.x; a2.y += w * v.y; a2.z += w * v.z; a2.w += w * v.w;
        v = vb[96 + lane];   a3.x += w * v.x; a3.y += w * v.y; a3.z += w * v.z; a3.w += w * v.w;
        if (lane < 16) {
            v = vb[128 + lane]; a4.x += w * v.x; a4.y += w * v.y; a4.z += w * v.z; a4.w += w * v.w;
        }
    }
    float rz = 1.f / (z + 1e-9f);
    a0.x *= rz; a0.y *= rz; a0.z *= rz; a0.w *= rz;
    a1.x *= rz; a1.y *= rz; a1.z *= rz; a1.w *= rz;
    a2.x *= rz; a2.y *= rz; a2.z *= rz; a2.w *= rz;
    a3.x *= rz; a3.y *= rz; a3.z *= rz; a3.w *= rz;
    a4.x *= rz; a4.y *= rz; a4.z *= rz; a4.w *= rz;
    float* sa = sAgg + wid * 576;
    ((float4*)sa)[lane] = a0; ((float4*)sa)[32 + lane] = a1;
    ((float4*)sa)[64 + lane] = a2; ((float4*)sa)[96 + lane] = a3;
    if (lane < 16) ((float4*)sa)[128 + lane] = a4;
    __syncwarp();

    float ao[9];
#pragma unroll
    for (int c = 0; c < 9; c++) {
        unsigned long long acc2 = 0ull;
        const unsigned long long* sav = (const unsigned long long*)(sa + c * 64);
#pragma unroll
        for (int jp = 0; jp < 32; jp++)
            ffma2(acc2, sav[jp], *(const unsigned long long*)&sWoP[jp * 32 + lane]);
        float x0, x1; unpack2(acc2, x0, x1);
        ao[c] = x0 + x1;
    }
    float hr[9];
#pragma unroll
    for (int c = 0; c < 9; c++) {
        float acc = 0.f;
#pragma unroll
        for (int o = 0; o < 32; o++) acc += __shfl_sync(FULLM, ao[c], o) * sW1[o * 32 + lane];
        hr[c] = acc;
    }
    float gate = silu_f(hr[0]);
    float nn0 = 0.f;
#pragma unroll
    for (int c = 0; c < 9; c++) {
        float t = hr[c] * gate;
        float acc = ao[c];
#pragma unroll
        for (int o = 0; o < 32; o++) acc += __shfl_sync(FULLM, t, o) * sW2[o * 32 + lane];
        out_node[n * 288 + c * 32 + lane] = acc;
        if (c == 0) nn0 = acc;
    }
    float ps = 0.f, pd = 0.f;
#pragma unroll
    for (int k = 0; k < 32; k++) {
        float u = __shfl_sync(FULLM, nn0, k);
        ps += u * sWe[k * 32 + lane];
        pd += u * sWe[(32 + k) * 32 + lane];
    }
    g_p[n * 64 + lane] = ps;
    g_p[n * 64 + 32 + lane] = pd;
}

// ---------------- edge output MLP: two-phase ef staging, residual half0 in regs ----------------
__global__ __launch_bounds__(256) void k_edge_out(
    const float* __restrict__ ef, const int* __restrict__ ei,
    const float* __restrict__ We1, const float* __restrict__ We2,
    float* __restrict__ out_edge) {
    __shared__ float s_ef[256 * 33];
    __shared__ float s_w1[2048];    // We1 rows 64..127
    __shared__ float s_w2[2048];    // We2 (32x64)
    int tid = threadIdx.x;
    int e0 = blockIdx.x * 256;
    for (int i = tid; i < 2048; i += 256) { s_w1[i] = We1[2048 + i]; s_w2[i] = We2[i]; }

    int e = e0 + tid;
    int s = ei[e], d = ei[NE + e];
    unsigned long long acc[16];
    {
        const float4* ps4 = (const float4*)(g_p + s * 64);
        const float4* pd4 = (const float4*)(g_p + d * 64 + 32);
#pragma unroll
        for (int i = 0; i < 8; i++) {
            float4 a = ps4[i], b = pd4[i];
            acc[2 * i] = pack2(a.x + b.x, a.y + b.y);
            acc[2 * i + 1] = pack2(a.z + b.z, a.w + b.w);
        }
    }
    float res0[32];
#pragma unroll
    for (int phase = 0; phase < 2; phase++) {
        __syncthreads();
        for (int i = tid; i < 2048; i += 256) {
            int r = i >> 3, c4 = i & 7;
            float4 v = *(const float4*)(ef + (size_t)(e0 + r) * 64 + phase * 32 + c4 * 4);
            float* dp = s_ef + r * 33 + c4 * 4;
            dp[0] = v.x; dp[1] = v.y; dp[2] = v.z; dp[3] = v.w;
        }
        __syncthreads();
        const float* efr = s_ef + tid * 33;
        const float* wb = s_w1 + phase * 32 * 32;
#pragma unroll 4
        for (int k = 0; k < 32; k++) {
            float a = efr[k];
            if (phase == 0) res0[k] = a;
            unsigned long long a2 = dup2(a);
            const unsigned long long* w = (const unsigned long long*)(wb + k * 32);
#pragma unroll
            for (int j = 0; j < 16; j++) ffma2(acc[j], a2, w[j]);
        }
    }
    float sv[32];
#pragma unroll
    for (int j = 0; j < 16; j++) {
        float x0, x1;
        unpack2(acc[j], x0, x1);
        sv[2 * j] = silu_f(x0);
        sv[2 * j + 1] = silu_f(x1);
    }
    const float* efr1 = s_ef + tid * 33;  // holds cols 32..63
#pragma unroll
    for (int half = 0; half < 2; half++) {
        unsigned long long o2[16];
#pragma unroll
        for (int t = 0; t < 16; t++) o2[t] = 0ull;
#pragma unroll 4
        for (int j = 0; j < 32; j++) {
            unsigned long long a2 = dup2(sv[j]);
            const unsigned long long* w = (const unsigned long long*)(s_w2 + j * 64 + half * 32);
#pragma unroll
            for (int t = 0; t < 16; t++) ffma2(o2[t], a2, w[t]);
        }
        float4* dp = (float4*)(out_edge + (size_t)e * 64 + half * 32);
#pragma unroll
        for (int t = 0; t < 8; t++) {
            float x0, x1, x2, x3;
            unpack2(o2[2 * t], x0, x1);
            unpack2(o2[2 * t + 1], x2, x3);
            float r0, r1, r2, r3;
            if (half == 0) { r0 = res0[4 * t]; r1 = res0[4 * t + 1]; r2 = res0[4 * t + 2]; r3 = res0[4 * t + 3]; }
            else { r0 = efr1[4 * t]; r1 = efr1[4 * t + 1]; r2 = efr1[4 * t + 2]; r3 = efr1[4 * t + 3]; }
            dp[t] = make_float4(x0 + r0, x1 + r1, x2 + r2, x3 + r3);
        }
    }
}

// ---------------- launch ----------------
extern "C" void kernel_launch(void* const* d_in, const int* in_sizes, int n_in,
                              void* d_out, int out_size) {
    const float* bb_emb = (const float*)d_in[0];
    const float* bb_rel = (const float*)d_in[1];
    const float* ef = (const float*)d_in[2];
    const int* ei = (const int*)d_in[3];
    const void* mask = d_in[4];
    const float* Wa1 = (const float*)d_in[5];
    const float* Wa2 = (const float*)d_in[6];
    const float* Wv = (const float*)d_in[7];
    const float* Wo = (const float*)d_in[8];
    const float* W1 = (const float*)d_in[9];
    const float* W2 = (const float*)d_in[10];
    const float* We1 = (const float*)d_in[11];
    const float* We2 = (const float*)d_in[12];
    float* out_node = (float*)d_out;
    float* out_edge = out_node + (size_t)NN * 288;

    k_mask_count<<<1250, 256>>>(mask, ei);
    k_scan<<<1, 1024>>>();
    k_node_prep<<<1250, 256>>>(bb_emb, bb_rel, Wa1, Wv);
    k_logits<<<1250, 256>>>(ef, ei, Wa1, Wa2);
    k_agg_node<<<1250, 256>>>(Wo, W1, W2, We1, out_node);
    k_edge_out<<<1250, 256>>>(ef, ei, We1, We2, out_edge);
}